// round 9
// baseline (speedup 1.0000x reference)
#include <cuda_runtime.h>
#include <cstdint>

// path[row][t] = 0.3 + (lam0[row] - 0.3) * 0.5^t   (closed form of the scan;
// clamp inactive after step 0; 0.5^t exact power of two via exponent bits).
//
// R7 probe, third submission (two broker timeouts, no kernel data yet):
// single change vs R6 (best, 23.84us): __stcs -> __stwt (write-through).
// R6 confirmed evict-first beats default write-back in the graph-replay
// steady state, but stcs lines still allocate dirty in L2, leaving a
// writeback residue that drains into the next replay's store stream.
// Write-through streams stores straight to DRAM: no dirty residue, no
// capacity-eviction collisions. Revert to R6 (__stcs) if this regresses.

static constexpr int HORIZON = 256;
static constexpr int T4_PER_ROW = HORIZON / 4;       // 64 float4 per row
static constexpr unsigned GRID = 2048;
static constexpr unsigned BLOCK = 256;
static constexpr unsigned STRIDE = GRID * BLOCK;     // 524288 = 2^19, multiple of 64
static constexpr unsigned N4 = 131072u * T4_PER_ROW; // 2^23 float4 total
static constexpr int ITERS = N4 / STRIDE;            // exactly 16

__global__ __launch_bounds__(BLOCK) void lyap_path_kernel(
    const float* __restrict__ lam0, float* __restrict__ out)
{
    unsigned idx4 = blockIdx.x * BLOCK + threadIdx.x;

    // Loop-invariant: t = 4 * (idx4 % 64) is fixed per thread (STRIDE % 64 == 0).
    int t = (int)(idx4 & (T4_PER_ROW - 1)) << 2;
    int e = 127 - t;
    const float f0 = (e > 0) ? __uint_as_float((unsigned)e << 23) : 0.0f;
    const float f1 = f0 * 0.5f;
    const float f2 = f1 * 0.5f;
    const float f3 = f2 * 0.5f;

    float4* __restrict__ out4 = reinterpret_cast<float4*>(out);
    const unsigned row_stride = STRIDE / T4_PER_ROW;  // 8192
    unsigned row = idx4 >> 6;

    #pragma unroll
    for (int i = 0; i < ITERS; i++, idx4 += STRIDE, row += row_stride) {
        float diff = __ldg(&lam0[row]) - 0.3f;

        float4 v;
        v.x = fmaf(diff, f0, 0.3f);
        v.y = fmaf(diff, f1, 0.3f);
        v.z = fmaf(diff, f2, 0.3f);
        v.w = fmaf(diff, f3, 0.3f);

        __stwt(&out4[idx4], v);   // write-through: no L2 dirty residue across replays
    }
}

extern "C" void kernel_launch(void* const* d_in, const int* in_sizes, int n_in,
                              void* d_out, int out_size)
{
    const float* lam0 = (const float*)d_in[0];
    float* out = (float*)d_out;

    lyap_path_kernel<<<GRID, BLOCK>>>(lam0, out);
}

// round 10
// speedup vs baseline: 1.1375x; 1.1375x over previous
#include <cuda_runtime.h>
#include <cstdint>

// path[row][t] = 0.3 + (lam0[row] - 0.3) * 0.5^t   (closed form of the scan;
// clamp inactive after step 0; 0.5^t exact power of two via exponent bits).
//
// R10: single change vs R6 (best, 23.84us): GRID 2048 -> 4096 (ITERS 16 -> 8).
// Store policy closed by measurement: write-back 25.06 / __stcs 23.84 /
// __stwt 26.21 -> __stcs kept. 2048 blocks over 148 SMs = 13.84/SM (14 vs 13,
// ~7% last-wave imbalance); 4096 -> 27.7/SM (28 vs 27, ~3.6%). Still exact:
// GRID*BLOCK = 2^20 divides n4 = 2^23, 8 unrolled STG.128 per thread.

static constexpr int HORIZON = 256;
static constexpr int T4_PER_ROW = HORIZON / 4;       // 64 float4 per row
static constexpr unsigned GRID = 4096;
static constexpr unsigned BLOCK = 256;
static constexpr unsigned STRIDE = GRID * BLOCK;     // 1048576 = 2^20, multiple of 64
static constexpr unsigned N4 = 131072u * T4_PER_ROW; // 2^23 float4 total
static constexpr int ITERS = N4 / STRIDE;            // exactly 8

__global__ __launch_bounds__(BLOCK) void lyap_path_kernel(
    const float* __restrict__ lam0, float* __restrict__ out)
{
    unsigned idx4 = blockIdx.x * BLOCK + threadIdx.x;

    // Loop-invariant: t = 4 * (idx4 % 64) is fixed per thread (STRIDE % 64 == 0).
    int t = (int)(idx4 & (T4_PER_ROW - 1)) << 2;
    int e = 127 - t;
    const float f0 = (e > 0) ? __uint_as_float((unsigned)e << 23) : 0.0f;
    const float f1 = f0 * 0.5f;
    const float f2 = f1 * 0.5f;
    const float f3 = f2 * 0.5f;

    float4* __restrict__ out4 = reinterpret_cast<float4*>(out);
    const unsigned row_stride = STRIDE / T4_PER_ROW;  // 16384
    unsigned row = idx4 >> 6;

    #pragma unroll
    for (int i = 0; i < ITERS; i++, idx4 += STRIDE, row += row_stride) {
        float diff = __ldg(&lam0[row]) - 0.3f;

        float4 v;
        v.x = fmaf(diff, f0, 0.3f);
        v.y = fmaf(diff, f1, 0.3f);
        v.z = fmaf(diff, f2, 0.3f);
        v.w = fmaf(diff, f3, 0.3f);

        __stcs(&out4[idx4], v);   // evict-first: overlap writeback with next replay
    }
}

extern "C" void kernel_launch(void* const* d_in, const int* in_sizes, int n_in,
                              void* d_out, int out_size)
{
    const float* lam0 = (const float*)d_in[0];
    float* out = (float*)d_out;

    lyap_path_kernel<<<GRID, BLOCK>>>(lam0, out);
}